// round 3
// baseline (speedup 1.0000x reference)
#include <cuda_runtime.h>
#include <cuda_bf16.h>
#include <math.h>

#define NB 2
#define SEQ 2048
#define DMODEL 1024
#define NHEAD 16
#define DHEAD 64
#define DFF 4096
#define NTOK (NB*SEQ)          // 4096

// ---------------- scratch (device globals; no runtime allocation) ----------------
__device__ float g_normed[(size_t)NTOK*DMODEL];
__device__ float g_q[(size_t)NTOK*DMODEL];
__device__ float g_k[(size_t)NTOK*DMODEL];
__device__ float g_v[(size_t)NTOK*DMODEL];
__device__ float g_scores[(size_t)NB*NHEAD*SEQ*SEQ];   // 512 MB
__device__ float g_ctx[(size_t)NTOK*DMODEL];
__device__ float g_hidden[(size_t)NTOK*DMODEL];
__device__ float g_ff1[(size_t)NTOK*DFF];
__device__ float g_ff2[(size_t)NTOK*DFF];
__device__ int   g_bucket[2*SEQ-1];

// ---------------- RMSNorm: one block per row of 1024 ----------------
__global__ void rmsnorm_kernel(const float* __restrict__ x, const float* __restrict__ w,
                               float* __restrict__ out)
{
    int row = blockIdx.x;
    const float* xr = x + (long long)row * DMODEL;
    float* orow = out + (long long)row * DMODEL;
    int tid = threadIdx.x;

    float s = 0.f;
    for (int i = tid; i < DMODEL; i += 256) { float v = xr[i]; s += v * v; }

    __shared__ float red[256];
    red[tid] = s; __syncthreads();
    for (int st = 128; st > 0; st >>= 1) {
        if (tid < st) red[tid] += red[tid + st];
        __syncthreads();
    }
    float scale = rsqrtf(red[0] / (float)DMODEL + 1e-6f);

    for (int i = tid; i < DMODEL; i += 256)
        orow[i] = xr[i] * scale * w[i];
}

// ---------------- T5 relative-position bucket table: index = (k - q) + (SEQ-1) ----
__global__ void bucket_kernel(int* __restrict__ table)
{
    int i = blockIdx.x * blockDim.x + threadIdx.x;
    if (i >= 2*SEQ - 1) return;
    int rel = i - (SEQ - 1);                // k - q
    int ret = (rel > 0) ? 16 : 0;           // num_buckets/2
    int n = abs(rel);
    int bucket;
    if (n < 8) {
        bucket = n;
    } else {
        int vl = 8 + (int)(logf((float)n / 8.0f) / logf(16.0f) * 8.0f);
        bucket = min(vl, 15);
    }
    table[i] = ret + bucket;
}

// ---------------- fused bias + mask + softmax over one score row ----------------
__global__ void softmax_kernel(float* __restrict__ scores,
                               const float* __restrict__ rel_bias,   // [32,16]
                               const int* __restrict__ bucket,
                               const float* __restrict__ mask)       // [NB,SEQ]
{
    int q = blockIdx.x, h = blockIdx.y, b = blockIdx.z;
    int tid = threadIdx.x;
    float* row = scores + (((long long)(b*NHEAD + h)) * SEQ + q) * SEQ;

    __shared__ float red[256];

    // pass 1: add bias + mask, find max
    float lmax = -1e30f;
    for (int k = tid; k < SEQ; k += 256) {
        float v = row[k]
                + rel_bias[bucket[k - q + (SEQ-1)] * NHEAD + h]
                + (1.0f - mask[b*SEQ + k]) * -10000.0f;
        row[k] = v;
        lmax = fmaxf(lmax, v);
    }
    red[tid] = lmax; __syncthreads();
    for (int st = 128; st > 0; st >>= 1) {
        if (tid < st) red[tid] = fmaxf(red[tid], red[tid + st]);
        __syncthreads();
    }
    float m = red[0];
    __syncthreads();

    // pass 2: exp + sum
    float lsum = 0.f;
    for (int k = tid; k < SEQ; k += 256) {
        float e = expf(row[k] - m);
        row[k] = e;
        lsum += e;
    }
    red[tid] = lsum; __syncthreads();
    for (int st = 128; st > 0; st >>= 1) {
        if (tid < st) red[tid] += red[tid + st];
        __syncthreads();
    }
    float inv = 1.0f / red[0];

    // pass 3: normalize
    for (int k = tid; k < SEQ; k += 256)
        row[k] *= inv;
}

// ---------------- gelu_new(a) * g, in place into a ----------------
__global__ void gelumul_kernel(float* __restrict__ a, const float* __restrict__ g,
                               long long n)
{
    long long i = (long long)blockIdx.x * blockDim.x + threadIdx.x;
    if (i >= n) return;
    float x = a[i];
    float t = tanhf(0.7978845608028654f * (x + 0.044715f * x * x * x));
    a[i] = 0.5f * x * (1.0f + t) * g[i];
}

// ---------------- generic 2-level-batched SGEMM: C = A@B (+Res) -------------------
// 128x128x8 tile, 8x8 per thread, 256 threads. TRANSB: B element (k,n)=B[n*ldb+k].
#define BM 128
#define BN 128
#define BK 8
#define TM 8
#define TN 8

template<bool TRANSB>
__global__ void __launch_bounds__(256)
gemm_kernel(const float* __restrict__ A, const float* __restrict__ B,
            const float* __restrict__ Res, float* __restrict__ C,
            int M, int N, int K, int lda, int ldb, int ldc, int ldr,
            int ZI,
            long long sAo, long long sAi, long long sBo, long long sBi,
            long long sCo, long long sCi, long long sRo, long long sRi)
{
    int z = blockIdx.z;
    int zo = z / ZI, zi = z - zo * ZI;
    A += zo * sAo + zi * sAi;
    B += zo * sBo + zi * sBi;
    C += zo * sCo + zi * sCi;
    if (Res) Res += zo * sRo + zi * sRi;

    __shared__ __align__(16) float As[BK][BM];
    __shared__ __align__(16) float Bs[BK][BN];

    int tid = threadIdx.x;
    int tx = tid & 15, ty = tid >> 4;
    int row0 = blockIdx.y * BM;
    int col0 = blockIdx.x * BN;

    float acc[TM][TN];
    #pragma unroll
    for (int i = 0; i < TM; i++)
        #pragma unroll
        for (int j = 0; j < TN; j++) acc[i][j] = 0.f;

    for (int k0 = 0; k0 < K; k0 += BK) {
        // load A tile (BM x BK), transposed into As[kk][m]
        #pragma unroll
        for (int it = 0; it < 4; it++) {
            int idx = tid + it * 256;
            int m  = idx >> 3;
            int kk = idx & 7;
            int gm = row0 + m, gk = k0 + kk;
            As[kk][m] = (gm < M && gk < K) ? A[(long long)gm * lda + gk] : 0.f;
        }
        // load B tile (BK x BN)
        #pragma unroll
        for (int it = 0; it < 4; it++) {
            int idx = tid + it * 256;
            int kk, n;
            if (!TRANSB) { kk = idx >> 7; n = idx & 127; }
            else         { n = idx >> 3; kk = idx & 7; }
            int gk = k0 + kk, gn = col0 + n;
            float v = 0.f;
            if (gk < K && gn < N)
                v = TRANSB ? B[(long long)gn * ldb + gk]
                           : B[(long long)gk * ldb + gn];
            Bs[kk][n] = v;
        }
        __syncthreads();

        #pragma unroll
        for (int kk = 0; kk < BK; kk++) {
            float4 a0 = *reinterpret_cast<const float4*>(&As[kk][ty * TM]);
            float4 a1 = *reinterpret_cast<const float4*>(&As[kk][ty * TM + 4]);
            float4 b0 = *reinterpret_cast<const float4*>(&Bs[kk][tx * TN]);
            float4 b1 = *reinterpret_cast<const float4*>(&Bs[kk][tx * TN + 4]);
            float av[8] = {a0.x, a0.y, a0.z, a0.w, a1.x, a1.y, a1.z, a1.w};
            float bv[8] = {b0.x, b0.y, b0.z, b0.w, b1.x, b1.y, b1.z, b1.w};
            #pragma unroll
            for (int i = 0; i < TM; i++)
                #pragma unroll
                for (int j = 0; j < TN; j++)
                    acc[i][j] += av[i] * bv[j];
        }
        __syncthreads();
    }

    #pragma unroll
    for (int i = 0; i < TM; i++) {
        int gm = row0 + ty * TM + i;
        if (gm >= M) continue;
        #pragma unroll
        for (int j = 0; j < TN; j++) {
            int gn = col0 + tx * TN + j;
            if (gn >= N) continue;
            float v = acc[i][j];
            if (Res) v += Res[(long long)gm * ldr + gn];
            C[(long long)gm * ldc + gn] = v;
        }
    }
}

// ---------------- host orchestration ----------------
extern "C" void kernel_launch(void* const* d_in, const int* in_sizes, int n_in,
                              void* d_out, int out_size)
{
    const float* hidden   = (const float*)d_in[0];
    const float* mask     = (const float*)d_in[1];
    const float* ln1_w    = (const float*)d_in[2];
    const float* wq       = (const float*)d_in[3];
    const float* wk       = (const float*)d_in[4];
    const float* wv       = (const float*)d_in[5];
    const float* rel_bias = (const float*)d_in[6];
    const float* wo       = (const float*)d_in[7];
    const float* ln2_w    = (const float*)d_in[8];
    const float* w1       = (const float*)d_in[9];
    const float* w2       = (const float*)d_in[10];
    const float* w_out    = (const float*)d_in[11];
    float* out = (float*)d_out;

    void* p;
    cudaGetSymbolAddress(&p, g_normed); float* normed = (float*)p;
    cudaGetSymbolAddress(&p, g_q);      float* q      = (float*)p;
    cudaGetSymbolAddress(&p, g_k);      float* k      = (float*)p;
    cudaGetSymbolAddress(&p, g_v);      float* v      = (float*)p;
    cudaGetSymbolAddress(&p, g_scores); float* scores = (float*)p;
    cudaGetSymbolAddress(&p, g_ctx);    float* ctx    = (float*)p;
    cudaGetSymbolAddress(&p, g_hidden); float* hid    = (float*)p;
    cudaGetSymbolAddress(&p, g_ff1);    float* ff1    = (float*)p;
    cudaGetSymbolAddress(&p, g_ff2);    float* ff2    = (float*)p;
    cudaGetSymbolAddress(&p, g_bucket); int*   bucket = (int*)p;

    const long long SD  = (long long)SEQ * DMODEL;   // per-batch token-plane stride
    const long long SS2 = (long long)SEQ * SEQ;      // per-head score plane

    // 1. RMSNorm #1
    rmsnorm_kernel<<<NTOK, 256>>>(hidden, ln1_w, normed);

    // 2. QKV projections: [4096,1024] x [1024,1024]
    dim3 gProj(DMODEL / BN, NTOK / BM, 1);
    gemm_kernel<false><<<gProj, 256>>>(normed, wq, nullptr, q,
        NTOK, DMODEL, DMODEL, DMODEL, DMODEL, DMODEL, 0,
        1, 0,0, 0,0, 0,0, 0,0);
    gemm_kernel<false><<<gProj, 256>>>(normed, wk, nullptr, k,
        NTOK, DMODEL, DMODEL, DMODEL, DMODEL, DMODEL, 0,
        1, 0,0, 0,0, 0,0, 0,0);
    gemm_kernel<false><<<gProj, 256>>>(normed, wv, nullptr, v,
        NTOK, DMODEL, DMODEL, DMODEL, DMODEL, DMODEL, 0,
        1, 0,0, 0,0, 0,0, 0,0);

    // 3. bucket table
    bucket_kernel<<<(2*SEQ - 1 + 255) / 256, 256>>>(bucket);

    // 4. scores = Q @ K^T per (b,h): M=N=2048, K=64
    dim3 gScore(SEQ / BN, SEQ / BM, NB * NHEAD);
    gemm_kernel<true><<<gScore, 256>>>(q, k, nullptr, scores,
        SEQ, SEQ, DHEAD, DMODEL, DMODEL, SEQ, 0,
        NHEAD, SD, DHEAD, SD, DHEAD, (long long)NHEAD * SS2, SS2, 0, 0);

    // 5. bias + mask + softmax (in place)
    dim3 gSm(SEQ, NHEAD, NB);
    softmax_kernel<<<gSm, 256>>>(scores, rel_bias, bucket, mask);

    // 6. ctx = probs @ V per (b,h): M=2048, N=64, K=2048
    dim3 gPV((DHEAD + BN - 1) / BN, SEQ / BM, NB * NHEAD);
    gemm_kernel<false><<<gPV, 256>>>(scores, v, nullptr, ctx,
        SEQ, DHEAD, SEQ, SEQ, DMODEL, DMODEL, 0,
        NHEAD, (long long)NHEAD * SS2, SS2, SD, DHEAD, SD, DHEAD, 0, 0);

    // 7. hidden = hidden_in + ctx @ wo
    gemm_kernel<false><<<gProj, 256>>>(ctx, wo, hidden, hid,
        NTOK, DMODEL, DMODEL, DMODEL, DMODEL, DMODEL, DMODEL,
        1, 0,0, 0,0, 0,0, 0,0);

    // 8. RMSNorm #2 (reuse normed buffer)
    rmsnorm_kernel<<<NTOK, 256>>>(hid, ln2_w, normed);

    // 9. ff1 = normed2 @ w1 ; ff2 = normed2 @ w2   [4096,1024]x[1024,4096]
    dim3 gFF(DFF / BN, NTOK / BM, 1);
    gemm_kernel<false><<<gFF, 256>>>(normed, w1, nullptr, ff1,
        NTOK, DFF, DMODEL, DMODEL, DFF, DFF, 0,
        1, 0,0, 0,0, 0,0, 0,0);
    gemm_kernel<false><<<gFF, 256>>>(normed, w2, nullptr, ff2,
        NTOK, DFF, DMODEL, DMODEL, DFF, DFF, 0,
        1, 0,0, 0,0, 0,0, 0,0);

    // 10. ff1 = gelu_new(ff1) * ff2
    long long nff = (long long)NTOK * DFF;
    gelumul_kernel<<<(unsigned)((nff + 255) / 256), 256>>>(ff1, ff2, nff);

    // 11. out = hidden + ff1 @ w_out   [4096,4096]x[4096,1024]
    gemm_kernel<false><<<gProj, 256>>>(ff1, w_out, hid, out,
        NTOK, DMODEL, DFF, DFF, DMODEL, DMODEL, DMODEL,
        1, 0,0, 0,0, 0,0, 0,0);
}

// round 6
// speedup vs baseline: 1.7464x; 1.7464x over previous
#include <cuda_runtime.h>
#include <cuda_bf16.h>
#include <math.h>

#define NB 2
#define SEQ 2048
#define DMODEL 1024
#define NHEAD 16
#define DHEAD 64
#define DFF 4096
#define NTOK (NB*SEQ)          // 4096

// ---------------- scratch (device globals; no runtime allocation) ----------------
__device__ float g_normed[(size_t)NTOK*DMODEL];
__device__ float g_q[(size_t)NTOK*DMODEL];
__device__ float g_k[(size_t)NTOK*DMODEL];
__device__ float g_v[(size_t)NTOK*DMODEL];
__device__ float g_scores[(size_t)NB*NHEAD*SEQ*SEQ];   // 512 MB
__device__ float g_ctx[(size_t)NTOK*DMODEL];
__device__ float g_hidden[(size_t)NTOK*DMODEL];
__device__ float g_ff1[(size_t)NTOK*DFF];
__device__ float g_ff2[(size_t)NTOK*DFF];
__device__ int   g_bucket[2*SEQ-1];

// ---------------- helpers ----------------
__device__ __forceinline__ unsigned f2tf32(float x)
{
    unsigned y;
    asm("cvt.rna.tf32.f32 %0, %1;" : "=r"(y) : "f"(x));
    return y;
}

// split x into tf32 hi + tf32 lo (3xTF32 trick: hi+lo ~= x to ~2^-22)
__device__ __forceinline__ void split_tf32(float x, unsigned& hi, unsigned& lo)
{
    unsigned h = f2tf32(x);
    float hf = __uint_as_float(h);     // tf32 register layout == fp32 bits, low mantissa zeroed
    hi = h;
    lo = f2tf32(x - hf);
}

__device__ __forceinline__ void mma_tf32(float* d, const unsigned* a, const unsigned* b)
{
    asm volatile(
        "mma.sync.aligned.m16n8k8.row.col.f32.tf32.tf32.f32 "
        "{%0,%1,%2,%3}, {%4,%5,%6,%7}, {%8,%9}, {%0,%1,%2,%3};\n"
        : "+f"(d[0]), "+f"(d[1]), "+f"(d[2]), "+f"(d[3])
        : "r"(a[0]), "r"(a[1]), "r"(a[2]), "r"(a[3]),
          "r"(b[0]), "r"(b[1]));
}

// ---------------- RMSNorm: one block per row of 1024 ----------------
__global__ void rmsnorm_kernel(const float* __restrict__ x, const float* __restrict__ w,
                               float* __restrict__ out)
{
    int row = blockIdx.x;
    const float* xr = x + (long long)row * DMODEL;
    float* orow = out + (long long)row * DMODEL;
    int tid = threadIdx.x;

    float s = 0.f;
    for (int i = tid; i < DMODEL; i += 256) { float v = xr[i]; s += v * v; }

    __shared__ float red[256];
    red[tid] = s; __syncthreads();
    for (int st = 128; st > 0; st >>= 1) {
        if (tid < st) red[tid] += red[tid + st];
        __syncthreads();
    }
    float scale = rsqrtf(red[0] / (float)DMODEL + 1e-6f);

    for (int i = tid; i < DMODEL; i += 256)
        orow[i] = xr[i] * scale * w[i];
}

// ---------------- T5 relative-position bucket table ----------------
__global__ void bucket_kernel(int* __restrict__ table)
{
    int i = blockIdx.x * blockDim.x + threadIdx.x;
    if (i >= 2*SEQ - 1) return;
    int rel = i - (SEQ - 1);                // k - q
    int ret = (rel > 0) ? 16 : 0;
    int n = abs(rel);
    int bucket;
    if (n < 8) {
        bucket = n;
    } else {
        int vl = 8 + (int)(logf((float)n / 8.0f) / logf(16.0f) * 8.0f);
        bucket = min(vl, 15);
    }
    table[i] = ret + bucket;
}

// ---------------- fused bias + mask + softmax, single pass (regs) ----------------
__global__ void softmax_kernel(float* __restrict__ scores,
                               const float* __restrict__ rel_bias,   // [32,16]
                               const int* __restrict__ bucket,
                               const float* __restrict__ mask)       // [NB,SEQ]
{
    int qv = blockIdx.x, h = blockIdx.y, b = blockIdx.z;
    int tid = threadIdx.x;
    float* row = scores + (((long long)(b*NHEAD + h)) * SEQ + qv) * SEQ;

    __shared__ float red[256];

    float vals[8];
    float lmax = -1e30f;
    #pragma unroll
    for (int j = 0; j < 8; j++) {
        int k = tid + j * 256;
        float v = row[k]
                + rel_bias[bucket[k - qv + (SEQ-1)] * NHEAD + h]
                + (1.0f - mask[b*SEQ + k]) * -10000.0f;
        vals[j] = v;
        lmax = fmaxf(lmax, v);
    }
    red[tid] = lmax; __syncthreads();
    for (int st = 128; st > 0; st >>= 1) {
        if (tid < st) red[tid] = fmaxf(red[tid], red[tid + st]);
        __syncthreads();
    }
    float m = red[0];
    __syncthreads();

    float lsum = 0.f;
    #pragma unroll
    for (int j = 0; j < 8; j++) {
        float e = expf(vals[j] - m);
        vals[j] = e;
        lsum += e;
    }
    red[tid] = lsum; __syncthreads();
    for (int st = 128; st > 0; st >>= 1) {
        if (tid < st) red[tid] += red[tid + st];
        __syncthreads();
    }
    float inv = 1.0f / red[0];

    #pragma unroll
    for (int j = 0; j < 8; j++)
        row[tid + j * 256] = vals[j] * inv;
}

// ---------------- gelu_new(a) * g, in place into a ----------------
__global__ void gelumul_kernel(float* __restrict__ a, const float* __restrict__ g,
                               long long n)
{
    long long i = (long long)blockIdx.x * blockDim.x + threadIdx.x;
    if (i >= n) return;
    float x = a[i];
    float t = tanhf(0.7978845608028654f * (x + 0.044715f * x * x * x));
    a[i] = 0.5f * x * (1.0f + t) * g[i];
}

// ---------------- 3xTF32 tensor-core GEMM: C = A@B (+Res) ----------------
// BM=128, BK=16, BN templated (128 or 64). 256 threads = 8 warps (4x2).
// Warp tile: 32 x (BN/2) = 2 x NT  m16n8k8 fragments.
// Operands stored fp32 in smem; split to (hi,lo) tf32 at fragment load;
// acc += ahi*bhi + alo*bhi + ahi*blo  (fp32-accurate).
// TRANSB: B element (k,n) = B[n*ldb + k].
template<int BN, bool TRANSB>
__global__ void __launch_bounds__(256)
mma_gemm(const float* __restrict__ A, const float* __restrict__ B,
         const float* __restrict__ Res, float* __restrict__ C,
         int M, int N, int K, int lda, int ldb, int ldc, int ldr,
         int ZI,
         long long sAo, long long sAi, long long sBo, long long sBi,
         long long sCo, long long sCi)
{
    constexpr int BM = 128, BK = 16;
    constexpr int ASTR = BK + 4;          // 20 floats -> conflict-free frag reads
    constexpr int BSTR = BN + 4;          // 132 / 68
    constexpr int WN = BN / 2;            // 64 / 32 cols per warp
    constexpr int NT = WN / 8;            // 8 / 4 n-tiles per warp
    constexpr int BLD = TRANSB ? 2 : (BN / 64);   // float4 loads per thread for B

    __shared__ __align__(16) float As[2][BM * ASTR];
    __shared__ __align__(16) float Bs[2][BK * BSTR];

    int z = blockIdx.z;
    int zo = z / ZI, zi = z - zo * ZI;
    A += zo * sAo + zi * sAi;
    B += zo * sBo + zi * sBi;
    C += zo * sCo + zi * sCi;

    int tid = threadIdx.x;
    int lane = tid & 31, wid = tid >> 5;
    int warp_m = wid >> 1, warp_n = wid & 1;
    int g = lane >> 2, t4 = lane & 3;
    int row0 = blockIdx.y * BM;
    int col0 = blockIdx.x * BN;

    float acc[2][NT][4];
    #pragma unroll
    for (int mi = 0; mi < 2; mi++)
        #pragma unroll
        for (int ni = 0; ni < NT; ni++)
            #pragma unroll
            for (int r = 0; r < 4; r++) acc[mi][ni][r] = 0.f;

    int arow[2], acol[2];
    #pragma unroll
    for (int it = 0; it < 2; it++) {
        int i = tid + it * 256;
        arow[it] = i >> 2;          // 0..127
        acol[it] = (i & 3) * 4;     // 0..12
    }

    float4 aR[2], bR[BLD];

    auto ldgA = [&](int k0) {
        #pragma unroll
        for (int it = 0; it < 2; it++)
            aR[it] = *reinterpret_cast<const float4*>(
                A + (long long)(row0 + arow[it]) * lda + k0 + acol[it]);
    };
    auto stsA = [&](int buf) {
        #pragma unroll
        for (int it = 0; it < 2; it++)
            *reinterpret_cast<float4*>(&As[buf][arow[it] * ASTR + acol[it]]) = aR[it];
    };
    auto ldgB = [&](int k0) {
        if (!TRANSB) {
            #pragma unroll
            for (int it = 0; it < BLD; it++) {
                int i = tid + it * 256;
                int kr = (BN == 128) ? (i >> 5) : (i >> 4);
                int nq = (BN == 128) ? ((i & 31) * 4) : ((i & 15) * 4);
                bR[it] = *reinterpret_cast<const float4*>(
                    B + (long long)(k0 + kr) * ldb + col0 + nq);
            }
        } else {
            #pragma unroll
            for (int it = 0; it < BLD; it++) {
                int i = tid + it * 256;
                int n = i >> 2, kq = (i & 3) * 4;
                bR[it] = *reinterpret_cast<const float4*>(
                    B + (long long)(col0 + n) * ldb + k0 + kq);
            }
        }
    };
    auto stsB = [&](int buf) {
        if (!TRANSB) {
            #pragma unroll
            for (int it = 0; it < BLD; it++) {
                int i = tid + it * 256;
                int kr = (BN == 128) ? (i >> 5) : (i >> 4);
                int nq = (BN == 128) ? ((i & 31) * 4) : ((i & 15) * 4);
                *reinterpret_cast<float4*>(&Bs[buf][kr * BSTR + nq]) = bR[it];
            }
        } else {
            #pragma unroll
            for (int it = 0; it < BLD; it++) {
                int i = tid + it * 256;
                int n = i >> 2, kq = (i & 3) * 4;
                Bs[buf][(kq + 0) * BSTR + n] = bR[it].x;
                Bs[buf][(kq + 1) * BSTR + n] = bR[it].y;
                Bs[buf][(kq + 2) * BSTR + n] = bR[it].z;
                Bs[buf][(kq + 3) * BSTR + n] = bR[it].w;
            }
        }
    };

    ldgA(0); ldgB(0);
    stsA(0); stsB(0);
    __syncthreads();

    int cur = 0;
    for (int k0 = 0; k0 < K; k0 += BK) {
        bool more = (k0 + BK) < K;
        if (more) { ldgA(k0 + BK); ldgB(k0 + BK); }

        #pragma unroll
        for (int kk = 0; kk < BK; kk += 8) {
            unsigned afh[2][4], afl[2][4];
            unsigned bfh[NT][2], bfl[NT][2];
            #pragma unroll
            for (int mi = 0; mi < 2; mi++) {
                int m = warp_m * 32 + mi * 16 + g;
                float a0 = As[cur][ m      * ASTR + kk + t4];
                float a1 = As[cur][(m + 8) * ASTR + kk + t4];
                float a2 = As[cur][ m      * ASTR + kk + t4 + 4];
                float a3 = As[cur][(m + 8) * ASTR + kk + t4 + 4];
                split_tf32(a0, afh[mi][0], afl[mi][0]);
                split_tf32(a1, afh[mi][1], afl[mi][1]);
                split_tf32(a2, afh[mi][2], afl[mi][2]);
                split_tf32(a3, afh[mi][3], afl[mi][3]);
            }
            #pragma unroll
            for (int ni = 0; ni < NT; ni++) {
                int n = warp_n * WN + ni * 8 + g;
                float b0 = Bs[cur][(kk + t4    ) * BSTR + n];
                float b1 = Bs[cur][(kk + t4 + 4) * BSTR + n];
                split_tf32(b0, bfh[ni][0], bfl[ni][0]);
                split_tf32(b1, bfh[ni][1], bfl[ni][1]);
            }
            #pragma unroll
            for (int mi = 0; mi < 2; mi++)
                #pragma unroll
                for (int ni = 0; ni < NT; ni++) {
                    mma_tf32(acc[mi][ni], afh[mi], bfh[ni]);
                    mma_tf32(acc[mi][ni], afl[mi], bfh[ni]);
                    mma_tf32(acc[mi][ni], afh[mi], bfl[ni]);
                }
        }

        if (more) { stsA(cur ^ 1); stsB(cur ^ 1); }
        __syncthreads();
        cur ^= 1;
    }

    // epilogue: d0,d1 at (r, c..c+1); d2,d3 at (r+8, c..c+1)
    #pragma unroll
    for (int mi = 0; mi < 2; mi++) {
        #pragma unroll
        for (int ni = 0; ni < NT; ni++) {
            int r = row0 + warp_m * 32 + mi * 16 + g;
            int c = col0 + warp_n * WN + ni * 8 + t4 * 2;
            float2 v0 = make_float2(acc[mi][ni][0], acc[mi][ni][1]);
            float2 v1 = make_float2(acc[mi][ni][2], acc[mi][ni][3]);
            if (Res) {
                float2 r0 = *reinterpret_cast<const float2*>(Res + (long long)r * ldr + c);
                float2 r1 = *reinterpret_cast<const float2*>(Res + (long long)(r + 8) * ldr + c);
                v0.x += r0.x; v0.y += r0.y;
                v1.x += r1.x; v1.y += r1.y;
            }
            *reinterpret_cast<float2*>(C + (long long)r * ldc + c) = v0;
            *reinterpret_cast<float2*>(C + (long long)(r + 8) * ldc + c) = v1;
        }
    }
}

// ---------------- host orchestration ----------------
extern "C" void kernel_launch(void* const* d_in, const int* in_sizes, int n_in,
                              void* d_out, int out_size)
{
    const float* hidden   = (const float*)d_in[0];
    const float* mask     = (const float*)d_in[1];
    const float* ln1_w    = (const float*)d_in[2];
    const float* wq       = (const float*)d_in[3];
    const float* wk       = (const float*)d_in[4];
    const float* wv       = (const float*)d_in[5];
    const float* rel_bias = (const float*)d_in[6];
    const float* wo       = (const float*)d_in[7];
    const float* ln2_w    = (const float*)d_in[8];
    const float* w1       = (const float*)d_in[9];
    const float* w2       = (const float*)d_in[10];
    const float* w_out    = (const float*)d_in[11];
    float* out = (float*)d_out;

    void* p;
    cudaGetSymbolAddress(&p, g_normed); float* normed = (float*)p;
    cudaGetSymbolAddress(&p, g_q);      float* q      = (float*)p;
    cudaGetSymbolAddress(&p, g_k);      float* k      = (float*)p;
    cudaGetSymbolAddress(&p, g_v);      float* v      = (float*)p;
    cudaGetSymbolAddress(&p, g_scores); float* scores = (float*)p;
    cudaGetSymbolAddress(&p, g_ctx);    float* ctx    = (float*)p;
    cudaGetSymbolAddress(&p, g_hidden); float* hid    = (float*)p;
    cudaGetSymbolAddress(&p, g_ff1);    float* ff1    = (float*)p;
    cudaGetSymbolAddress(&p, g_ff2);    float* ff2    = (float*)p;
    cudaGetSymbolAddress(&p, g_bucket); int*   bucket = (int*)p;

    const long long SD  = (long long)SEQ * DMODEL;   // per-batch token-plane stride
    const long long SS2 = (long long)SEQ * SEQ;      // per-head score plane

    // 1. RMSNorm #1
    rmsnorm_kernel<<<NTOK, 256>>>(hidden, ln1_w, normed);

    // 2. QKV projections: [4096,1024] x [1024,1024]
    dim3 gProj(DMODEL / 128, NTOK / 128, 1);
    mma_gemm<128,false><<<gProj, 256>>>(normed, wq, nullptr, q,
        NTOK, DMODEL, DMODEL, DMODEL, DMODEL, DMODEL, 0,
        1, 0,0, 0,0, 0,0);
    mma_gemm<128,false><<<gProj, 256>>>(normed, wk, nullptr, k,
        NTOK, DMODEL, DMODEL, DMODEL, DMODEL, DMODEL, 0,
        1, 0,0, 0,0, 0,0);
    mma_gemm<128,false><<<gProj, 256>>>(normed, wv, nullptr, v,
        NTOK, DMODEL, DMODEL, DMODEL, DMODEL, DMODEL, 0,
        1, 0,0, 0,0, 0,0);

    // 3. bucket table
    bucket_kernel<<<(2*SEQ - 1 + 255) / 256, 256>>>(bucket);

    // 4. scores = Q @ K^T per (b,h): M=N=2048, K=64
    dim3 gScore(SEQ / 128, SEQ / 128, NB * NHEAD);
    mma_gemm<128,true><<<gScore, 256>>>(q, k, nullptr, scores,
        SEQ, SEQ, DHEAD, DMODEL, DMODEL, SEQ, 0,
        NHEAD, SD, DHEAD, SD, DHEAD, (long long)NHEAD * SS2, SS2);

    // 5. bias + mask + softmax (single pass, in place)
    dim3 gSm(SEQ, NHEAD, NB);
    softmax_kernel<<<gSm, 256>>>(scores, rel_bias, bucket, mask);

    // 6. ctx = probs @ V per (b,h): M=2048, N=64, K=2048
    dim3 gPV(1, SEQ / 128, NB * NHEAD);
    mma_gemm<64,false><<<gPV, 256>>>(scores, v, nullptr, ctx,
        SEQ, DHEAD, SEQ, SEQ, DMODEL, DMODEL, 0,
        NHEAD, (long long)NHEAD * SS2, SS2, SD, DHEAD, SD, DHEAD);

    // 7. hidden = hidden_in + ctx @ wo
    mma_gemm<128,false><<<gProj, 256>>>(ctx, wo, hidden, hid,
        NTOK, DMODEL, DMODEL, DMODEL, DMODEL, DMODEL, DMODEL,
        1, 0,0, 0,0, 0,0);

    // 8. RMSNorm #2 (reuse normed buffer)
    rmsnorm_kernel<<<NTOK, 256>>>(hid, ln2_w, normed);

    // 9. ff1 = normed2 @ w1 ; ff2 = normed2 @ w2   [4096,1024]x[1024,4096]
    dim3 gFF(DFF / 128, NTOK / 128, 1);
    mma_gemm<128,false><<<gFF, 256>>>(normed, w1, nullptr, ff1,
        NTOK, DFF, DMODEL, DMODEL, DFF, DFF, 0,
        1, 0,0, 0,0, 0,0);
    mma_gemm<128,false><<<gFF, 256>>>(normed, w2, nullptr, ff2,
        NTOK, DFF, DMODEL, DMODEL, DFF, DFF, 0,
        1, 0,0, 0,0, 0,0);

    // 10. ff1 = gelu_new(ff1) * ff2
    long long nff = (long long)NTOK * DFF;
    gelumul_kernel<<<(unsigned)((nff + 255) / 256), 256>>>(ff1, ff2, nff);

    // 11. out = hidden + ff1 @ w_out   [4096,4096]x[4096,1024]
    mma_gemm<128,false><<<gProj, 256>>>(ff1, w_out, hid, out,
        NTOK, DMODEL, DFF, DFF, DMODEL, DMODEL, DMODEL,
        1, 0,0, 0,0, 0,0);
}